// round 6
// baseline (speedup 1.0000x reference)
#include <cuda_runtime.h>
#include <cuda_fp16.h>
#include <cstdint>

#define CIN   672
#define COUT  128
#define HW    49
#define NB    4
#define NREAL 196         // NB*HW
#define NSP   56          // per-batch padded spatial
#define NPAD  224
#define KC    32
#define NKC   21
#define THREADS 640       // 16 consumer warps + 4 producer warps
#define GRID  256

#define LDAW  352         // A row stride in words (88 quads, mult of 8 -> swizzle ok)
#define LDBW  20          // B row stride in words (5 quads -> conflict-free LDSM)

#define OFF_SS 0                       // float2[672] = 1344 words
#define OFF_A  1344
#define A_WORDS (COUT*LDAW)            // 45056
#define OFF_B0 (OFF_A + A_WORDS)       // 46400
#define B_WORDS (NPAD*LDBW)            // 4480
#define OFF_B1 (OFF_B0 + B_WORDS)
#define SMEM_WORDS (OFF_B1 + B_WORDS)  // 55360
#define SMEM_BYTES (SMEM_WORDS*4)      // 221440
#define PS 225

// named barrier ids
#define BAR_FULL0 1
#define BAR_FREE0 3
#define BAR_CONS  5

__device__ __forceinline__ void bar_sync(int id, int cnt) {
    asm volatile("bar.sync %0, %1;" :: "r"(id), "r"(cnt) : "memory");
}
__device__ __forceinline__ void bar_arrive(int id, int cnt) {
    asm volatile("bar.arrive %0, %1;" :: "r"(id), "r"(cnt) : "memory");
}
__device__ __forceinline__ void hmma16816(float c[4],
    uint32_t a0, uint32_t a1, uint32_t a2, uint32_t a3, uint32_t b0, uint32_t b1)
{
    asm volatile(
        "mma.sync.aligned.m16n8k16.row.col.f32.f16.f16.f32 "
        "{%0,%1,%2,%3}, {%4,%5,%6,%7}, {%8,%9}, {%0,%1,%2,%3};"
        : "+f"(c[0]), "+f"(c[1]), "+f"(c[2]), "+f"(c[3])
        : "r"(a0), "r"(a1), "r"(a2), "r"(a3), "r"(b0), "r"(b1));
}
__device__ __forceinline__ void ldsm_x4(uint32_t& r0, uint32_t& r1,
                                        uint32_t& r2, uint32_t& r3, uint32_t addr)
{
    asm volatile("ldmatrix.sync.aligned.m8n8.x4.shared.b16 {%0,%1,%2,%3}, [%4];"
                 : "=r"(r0), "=r"(r1), "=r"(r2), "=r"(r3) : "r"(addr));
}
__device__ __forceinline__ void ldsm_x2(uint32_t& r0, uint32_t& r1, uint32_t addr)
{
    asm volatile("ldmatrix.sync.aligned.m8n8.x2.shared.b16 {%0,%1}, [%2];"
                 : "=r"(r0), "=r"(r1) : "r"(addr));
}
__device__ __forceinline__ uint32_t pack_h2(float lo, float hi) {
    __half2 h = __floats2half2_rn(lo, hi);
    return *reinterpret_cast<uint32_t*>(&h);
}
__device__ __forceinline__ uint32_t smem_u32(const void* p) {
    uint32_t a;
    asm("{ .reg .u64 t; cvta.to.shared.u64 t, %1; cvt.u32.u64 %0, t; }" : "=r"(a) : "l"(p));
    return a;
}

extern __shared__ uint32_t sm[];

__global__ void __launch_bounds__(THREADS, 1)
bn_conv_ws(const float* __restrict__ x,
           const float* __restrict__ gamma,
           const float* __restrict__ beta,
           const float* __restrict__ rmean,
           const float* __restrict__ rvar,
           const float* __restrict__ W,
           float* __restrict__ out)
{
    const int tid  = threadIdx.x;
    const int wid  = tid >> 5;
    const int lane = tid & 31;
    const uint32_t sb = smem_u32(sm);

    float2* ssc = (float2*)(sm + OFF_SS);
    const float* sscf = (const float*)ssc;

    // ======== prologue (all 640 threads) ========
    for (int c = tid; c < CIN; c += THREADS) {
        float inv = rsqrtf(rvar[c] + 1e-5f);
        float s = gamma[c] * inv;
        ssc[c] = make_float2(s, beta[c] - rmean[c] * s);
    }
    for (int i = tid; i < 2 * B_WORDS; i += THREADS) sm[OFF_B0 + i] = 0u;

    // stage full W as fp16, quad-swizzled: 10752 quads
    #pragma unroll
    for (int it = 0; it < 17; it++) {
        int u = tid + it * THREADS;
        if (u < COUT * 84) {
            int m = u / 84, qk = u - m * 84;
            const float* ws = W + (size_t)m * CIN + qk * 8;
            float4 w0 = *(const float4*)ws;
            float4 w1 = *(const float4*)(ws + 4);
            uint4 q;
            q.x = pack_h2(w0.x, w0.y); q.y = pack_h2(w0.z, w0.w);
            q.z = pack_h2(w1.x, w1.y); q.w = pack_h2(w1.z, w1.w);
            int qpos = (qk & ~7) | ((qk & 7) ^ (m & 7));
            *(uint4*)(sm + OFF_A + m * LDAW + qpos * 4) = q;
        }
    }
    const float* xb = x + (size_t)blockIdx.x * NB * CIN * HW;
    __syncthreads();

    if (wid < 16) {
        // ==================== CONSUMERS ====================
        const int g = lane >> 2, t = lane & 3;
        const int m_base = (wid & 3) * 32;     // 4 warps over M=128
        const int n0     = (wid >> 2) * 56;    // 4 warps over N=224
        const int arow  = (lane & 7) + ((lane >> 3) & 1) * 8;
        const int aqsel = (lane >> 4) & 1;
        const int alow  = lane & 7;
        const int brow  = (lane & 7) + ((lane >> 4) & 1) * 8;
        const int bqsel = (lane >> 3) & 1;

        float acc[2][7][4];
        #pragma unroll
        for (int mt = 0; mt < 2; mt++)
            #pragma unroll
            for (int nt = 0; nt < 7; nt++)
                #pragma unroll
                for (int i = 0; i < 4; i++) acc[mt][nt][i] = 0.0f;

        #pragma unroll 1
        for (int kc = 0; kc < NKC; kc++) {
            const int s = kc & 1;
            bar_sync(BAR_FULL0 + s, THREADS);
            const uint32_t boffw = s ? OFF_B1 : OFF_B0;
            #pragma unroll
            for (int ks = 0; ks < 2; ks++) {
                const int qk = kc * 4 + ks * 2 + aqsel;
                const int qpos = (qk & ~7) | ((qk & 7) ^ alow);
                uint32_t a[2][4];
                #pragma unroll
                for (int mt = 0; mt < 2; mt++) {
                    uint32_t addr = sb + 4 * (OFF_A + (m_base + mt * 16 + arow) * LDAW + qpos * 4);
                    ldsm_x4(a[mt][0], a[mt][1], a[mt][2], a[mt][3], addr);
                }
                uint32_t b[7][2];
                const uint32_t bbase = sb + 4 * (boffw + (n0 + brow) * LDBW + (ks * 2 + bqsel) * 4);
                #pragma unroll
                for (int np = 0; np < 3; np++) {
                    ldsm_x4(b[2 * np][0], b[2 * np][1], b[2 * np + 1][0], b[2 * np + 1][1],
                            bbase + 4 * (np * 16 * LDBW));
                }
                {
                    uint32_t addr6 = bbase + 4 * (6 * 8 * LDBW);
                    if (brow >= 8) addr6 -= 4 * (8 * LDBW);
                    ldsm_x2(b[6][0], b[6][1], addr6);
                }
                #pragma unroll
                for (int nt = 0; nt < 7; nt++) {
                    hmma16816(acc[0][nt], a[0][0], a[0][1], a[0][2], a[0][3], b[nt][0], b[nt][1]);
                    hmma16816(acc[1][nt], a[1][0], a[1][1], a[1][2], a[1][3], b[nt][0], b[nt][1]);
                }
            }
            bar_arrive(BAR_FREE0 + s, THREADS);
        }

        // all consumers done with W reads before overlaying payload
        bar_sync(BAR_CONS, 512);

        float* P = (float*)sm;
        #pragma unroll
        for (int mt = 0; mt < 2; mt++) {
            const int rb = m_base + mt * 16 + g;
            #pragma unroll
            for (int nt = 0; nt < 7; nt++) {
                const int cb = n0 + nt * 8 + 2 * t;
                P[rb * PS + cb]           = acc[mt][nt][0];
                P[rb * PS + cb + 1]       = acc[mt][nt][1];
                P[(rb + 8) * PS + cb]     = acc[mt][nt][2];
                P[(rb + 8) * PS + cb + 1] = acc[mt][nt][3];
            }
        }
    } else {
        // ==================== PRODUCERS (4 warps, 128 threads) ====================
        const int ptid = tid - 512;
        int xoffa[13];
        int pwa[13];                     // bw | (p<<16)
        #pragma unroll
        for (int j = 0; j < 13; j++) {
            int i = ptid + j * 128;
            if (i > 1567) i = 1567;
            int p = i / NREAL;
            int n = i - p * NREAL;
            int bloc = n / HW, s = n - bloc * HW;
            xoffa[j] = (bloc * CIN + p * 4) * HW + s;
            pwa[j]   = ((bloc * NSP + s) * LDBW + p * 2) | (p << 16);
        }
        const bool v12 = (ptid < 32);

        float xv[13][4];
        // preload chunk 0
        #pragma unroll
        for (int j = 0; j < 13; j++) {
            if (j < 12 || v12) {
                const float* px = xb + xoffa[j];
                xv[j][0] = px[0];
                xv[j][1] = px[HW];
                xv[j][2] = px[2 * HW];
                xv[j][3] = px[3 * HW];
            }
        }

        #pragma unroll 1
        for (int kc = 0; kc < NKC; kc++) {
            const int s = kc & 1;
            if (kc >= 2) bar_sync(BAR_FREE0 + s, THREADS);

            uint32_t* Bn = sm + (s ? OFF_B1 : OFF_B0);
            const int kcb = kc * KC;
            #pragma unroll
            for (int j = 0; j < 13; j++) {
                if (j < 12 || v12) {
                    const int pw = pwa[j];
                    const int c = kcb + ((pw >> 16) << 2);
                    float4 s0 = *(const float4*)(sscf + 2 * c);
                    float4 s1 = *(const float4*)(sscf + 2 * c + 4);
                    float h0 = fmaxf(fmaf(xv[j][0], s0.x, s0.y), 0.0f);
                    float h1 = fmaxf(fmaf(xv[j][1], s0.z, s0.w), 0.0f);
                    float h2 = fmaxf(fmaf(xv[j][2], s1.x, s1.y), 0.0f);
                    float h3 = fmaxf(fmaf(xv[j][3], s1.z, s1.w), 0.0f);
                    uint2 hb;
                    hb.x = pack_h2(h0, h1);
                    hb.y = pack_h2(h2, h3);
                    *(uint2*)(Bn + (pw & 0xFFFF)) = hb;
                }
            }
            bar_arrive(BAR_FULL0 + s, THREADS);

            // prefetch next chunk's x (a full chunk ahead of its use)
            if (kc < NKC - 1) {
                const int xadd = (kc + 1) * (KC * HW);
                #pragma unroll
                for (int j = 0; j < 13; j++) {
                    if (j < 12 || v12) {
                        const float* px = xb + xoffa[j] + xadd;
                        xv[j][0] = px[0];
                        xv[j][1] = px[HW];
                        xv[j][2] = px[2 * HW];
                        xv[j][3] = px[3 * HW];
                    }
                }
            }
        }
    }

    __syncthreads();   // payload P complete

    // ---- coalesced store (all 640 threads) ----
    const float* P = (const float*)sm;
    float* ob = out + (size_t)blockIdx.x * NB * COUT * HW;
    #pragma unroll 5
    for (int it = 0; it < 40; it++) {
        int f = tid + it * THREADS;
        if (f < NB * COUT * HW) {
            int bloc = f / (COUT * HW);
            int r = f - bloc * (COUT * HW);
            int o = r / HW;
            int s = r - o * HW;
            ob[f] = P[o * PS + bloc * NSP + s];
        }
    }
}

extern "C" void kernel_launch(void* const* d_in, const int* in_sizes, int n_in,
                              void* d_out, int out_size)
{
    const float* x     = (const float*)d_in[0];
    const float* gamma = (const float*)d_in[1];
    const float* beta  = (const float*)d_in[2];
    const float* rmean = (const float*)d_in[3];
    const float* rvar  = (const float*)d_in[4];
    const float* W     = (const float*)d_in[5];
    float* out = (float*)d_out;

    cudaFuncSetAttribute(bn_conv_ws,
                         cudaFuncAttributeMaxDynamicSharedMemorySize, SMEM_BYTES);
    bn_conv_ws<<<GRID, THREADS, SMEM_BYTES>>>(x, gamma, beta, rmean, rvar, W, out);
}

// round 7
// speedup vs baseline: 1.9389x; 1.9389x over previous
#include <cuda_runtime.h>
#include <cuda_fp16.h>
#include <cstdint>

#define CIN   672
#define COUT  128
#define HW    49
#define NB    2
#define NREAL 98          // NB*HW
#define NPAD  112
#define KC    32
#define NKC   21
#define GRID  512

#define LDA 20            // A row stride (half2 words): conflict-free frag reads
#define LDB 24            // B row stride (half2 words): conflict-free frag reads
#define A_WORDS (COUT*LDA)   // 2560
#define B_WORDS (NPAD*LDB)   // 2688

// word offsets in dynamic smem
#define OFF_SS 0                         // float2[672] (scale, shift) = 1344 words
#define OFF_A0 1344
#define OFF_A1 (OFF_A0 + A_WORDS)
#define OFF_B0 (OFF_A1 + A_WORDS)
#define OFF_B1 (OFF_B0 + B_WORDS)
#define PIPE_WORDS (OFF_B1 + B_WORDS)    // 11840 words
#define PS 113
#define P_WORDS (COUT*PS)                // 14464 words
#define SMEM_WORDS (P_WORDS > PIPE_WORDS ? P_WORDS : PIPE_WORDS)
#define SMEM_BYTES (SMEM_WORDS*4)        // 57856 -> 2 CTAs/SM

__device__ __forceinline__ void hmma16816(float c[4],
    uint32_t a0, uint32_t a1, uint32_t a2, uint32_t a3, uint32_t b0, uint32_t b1)
{
    asm volatile(
        "mma.sync.aligned.m16n8k16.row.col.f32.f16.f16.f32 "
        "{%0,%1,%2,%3}, {%4,%5,%6,%7}, {%8,%9}, {%0,%1,%2,%3};"
        : "+f"(c[0]), "+f"(c[1]), "+f"(c[2]), "+f"(c[3])
        : "r"(a0), "r"(a1), "r"(a2), "r"(a3), "r"(b0), "r"(b1));
}
__device__ __forceinline__ uint32_t pack_h2(float lo, float hi) {
    __half2 h = __floats2half2_rn(lo, hi);
    return *reinterpret_cast<uint32_t*>(&h);
}
__device__ __forceinline__ void prefetch_l2(const void* p) {
    asm volatile("prefetch.global.L2 [%0];" :: "l"(p));
}
__device__ __forceinline__ uint32_t smem_u32(const void* p) {
    uint32_t a;
    asm("{ .reg .u64 t; cvta.to.shared.u64 t, %1; cvt.u32.u64 %0, t; }" : "=r"(a) : "l"(p));
    return a;
}
__device__ __forceinline__ void cp16(uint32_t dst, const void* src) {
    asm volatile("cp.async.cg.shared.global [%0], [%1], 16;" :: "r"(dst), "l"(src) : "memory");
}

extern __shared__ uint32_t sm[];

__global__ void __launch_bounds__(256, 2)
bn_conv_f16p(const float* __restrict__ x,
             const float* __restrict__ gamma,
             const float* __restrict__ beta,
             const float* __restrict__ rmean,
             const float* __restrict__ rvar,
             const float* __restrict__ W,
             float* __restrict__ out)
{
    const int tid  = threadIdx.x;
    const int wid  = tid >> 5;
    const int lane = tid & 31;
    const int g = lane >> 2, t = lane & 3;
    const int m0 = (wid & 3) * 32;        // 4 warps over M=128
    const int n0 = (wid >> 2) * 56;       // 2 warps over N=112

    float2* ssc = (float2*)(sm + OFF_SS);
    const float* sscf = (const float*)ssc;

    // ---- prologue: BN fold + zero B buffers ----
    for (int c = tid; c < CIN; c += 256) {
        float inv = rsqrtf(rvar[c] + 1e-5f);
        float s = gamma[c] * inv;
        ssc[c] = make_float2(s, beta[c] - rmean[c] * s);
    }
    for (int i = tid; i < 2 * B_WORDS; i += 256) sm[OFF_B0 + i] = 0u;

    const float* xb = x + (size_t)blockIdx.x * NB * CIN * HW;

    // L2-prefetch x chunks 0 and 1 (each chunk = 2 contiguous 6272B regions)
    if (tid < 196) {
        int kch = tid / 98;               // chunk 0 or 1
        int r   = tid - kch * 98;
        int bloc = r / 49, l = r - bloc * 49;
        prefetch_l2(xb + ((size_t)bloc * CIN + kch * KC) * HW + l * 32);
    }

    // ---- per-thread staging constants ----
    int xoff[4], bsts[4], klr[4];
    #pragma unroll
    for (int j = 0; j < 4; j++) {
        int i = tid + j * 256;
        if (i > 783) i = 783;
        int p = i / 98;
        int n = i - 98 * p;
        int tp = p & 3, ks = p >> 2;
        int kl = ks * 16 + tp * 2;
        int b = (n >= HW) ? 1 : 0;
        int s = n - HW * b;
        xoff[j] = (b * CIN + kl) * HW + s;
        bsts[j] = n * LDB + 2 * (p ^ (n & 7));
        klr[j]  = kl;
    }
    const bool v3 = (tid < 16);

    int woff[4], asts[4];
    #pragma unroll
    for (int it = 0; it < 4; it++) {
        int idx = tid + it * 256;
        int m = idx >> 3, q = idx & 7;
        woff[it] = m * CIN + 4 * q;
        asts[it] = m * LDA + 2 * q;
    }

    __syncthreads();

    float acc[2][7][4];
    #pragma unroll
    for (int mt = 0; mt < 2; mt++)
        #pragma unroll
        for (int nt = 0; nt < 7; nt++)
            #pragma unroll
            for (int i = 0; i < 4; i++) acc[mt][nt][i] = 0.0f;

    const int ar00 = (m0 + g) * LDA;
    const int ar01 = (m0 + g + 8) * LDA;
    const int ar10 = (m0 + 16 + g) * LDA;
    const int ar11 = (m0 + 24 + g) * LDA;
    const int bnb  = (n0 + g) * LDB;

    float xv[4][4];

    #pragma unroll 1
    for (int kc = -1; kc < NKC; kc++) {
        const int kcn = kc + 1;

        // ---- issue x LDGs for chunk kcn (should now be L2-resident) ----
        if (kcn < NKC) {
            const int xadd = kcn * (KC * HW);
            #pragma unroll
            for (int j = 0; j < 4; j++) {
                if (j < 3 || v3) {
                    const float* px = xb + xoff[j] + xadd;
                    xv[j][0] = px[0];
                    xv[j][1] = px[HW];
                    xv[j][2] = px[8 * HW];
                    xv[j][3] = px[9 * HW];
                }
            }
        }

        // ---- L2-prefetch x chunk kcn+1 (2 chunks ahead of use) ----
        if (kcn + 1 < NKC && tid < 98) {
            int bloc = tid / 49, l = tid - bloc * 49;
            prefetch_l2(xb + ((size_t)bloc * CIN + (kcn + 1) * KC) * HW + l * 32);
        }

        // ---- MMA on chunk kc ----
        if (kc >= 0) {
            const uint32_t* As = sm + ((kc & 1) ? OFF_A1 : OFF_A0);
            const uint32_t* Bs = sm + ((kc & 1) ? OFF_B1 : OFF_B0);
            #pragma unroll
            for (int ks = 0; ks < 2; ks++) {
                const int ka = ks * 8 + t;
                uint32_t a0[4], a1[4];
                a0[0] = As[ar00 + ka];     a0[1] = As[ar01 + ka];
                a0[2] = As[ar00 + ka + 4]; a0[3] = As[ar01 + ka + 4];
                a1[0] = As[ar10 + ka];     a1[1] = As[ar11 + ka];
                a1[2] = As[ar10 + ka + 4]; a1[3] = As[ar11 + ka + 4];
                const int bsw = bnb + 2 * ((ks * 4 + t) ^ g);
                #pragma unroll
                for (int nt = 0; nt < 7; nt++) {
                    uint2 b = *(const uint2*)&Bs[bsw + nt * 8 * LDB];
                    hmma16816(acc[0][nt], a0[0], a0[1], a0[2], a0[3], b.x, b.y);
                    hmma16816(acc[1][nt], a1[0], a1[1], a1[2], a1[3], b.x, b.y);
                }
            }
        }

        // ---- stage chunk kcn into the other buffer ----
        if (kcn < NKC) {
            uint32_t* An = sm + ((kcn & 1) ? OFF_A1 : OFF_A0);
            uint32_t* Bn = sm + ((kcn & 1) ? OFF_B1 : OFF_B0);

            const float* Wc = W + kcn * KC;
            #pragma unroll
            for (int it = 0; it < 4; it++) {
                float4 w = *(const float4*)(Wc + woff[it]);
                uint2 hw;
                hw.x = pack_h2(w.x, w.y);
                hw.y = pack_h2(w.z, w.w);
                *(uint2*)(An + asts[it]) = hw;
            }

            #pragma unroll
            for (int j = 0; j < 4; j++) {
                if (j < 3 || v3) {
                    const int c = kcn * KC + klr[j];
                    float4 s0 = *(const float4*)(sscf + 2 * c);
                    float4 s1 = *(const float4*)(sscf + 2 * (c + 8));
                    float h0 = fmaxf(fmaf(xv[j][0], s0.x, s0.y), 0.0f);
                    float h1 = fmaxf(fmaf(xv[j][1], s0.z, s0.w), 0.0f);
                    float h2 = fmaxf(fmaf(xv[j][2], s1.x, s1.y), 0.0f);
                    float h3 = fmaxf(fmaf(xv[j][3], s1.z, s1.w), 0.0f);
                    uint2 hb;
                    hb.x = pack_h2(h0, h1);
                    hb.y = pack_h2(h2, h3);
                    *(uint2*)(Bn + bsts[j]) = hb;
                }
            }
        }
        __syncthreads();
    }

    // ---- epilogue: acc -> SMEM payload -> coalesced vector STG ----
    float* P = (float*)sm;
    #pragma unroll
    for (int mt = 0; mt < 2; mt++) {
        const int rb = m0 + mt * 16 + g;
        #pragma unroll
        for (int nt = 0; nt < 7; nt++) {
            const int cb = n0 + nt * 8 + 2 * t;
            P[rb * PS + cb]           = acc[mt][nt][0];
            P[rb * PS + cb + 1]       = acc[mt][nt][1];
            P[(rb + 8) * PS + cb]     = acc[mt][nt][2];
            P[(rb + 8) * PS + cb + 1] = acc[mt][nt][3];
        }
    }
    __syncthreads();

    float* ob = out + (size_t)blockIdx.x * NB * COUT * HW;
    #pragma unroll
    for (int it = 0; it < 13; it++) {
        int f0 = (tid + it * 256) * 4;
        if (f0 < NB * COUT * HW) {
            float4 v;
            #pragma unroll
            for (int e = 0; e < 4; e++) {
                int f = f0 + e;
                int b = (f >= COUT * HW) ? 1 : 0;
                int r = f - b * (COUT * HW);
                int o = r / HW;
                int s = r - o * HW;
                ((float*)&v)[e] = P[o * PS + b * HW + s];
            }
            *(float4*)(ob + f0) = v;
        }
    }
}

extern "C" void kernel_launch(void* const* d_in, const int* in_sizes, int n_in,
                              void* d_out, int out_size)
{
    const float* x     = (const float*)d_in[0];
    const float* gamma = (const float*)d_in[1];
    const float* beta  = (const float*)d_in[2];
    const float* rmean = (const float*)d_in[3];
    const float* rvar  = (const float*)d_in[4];
    const float* W     = (const float*)d_in[5];
    float* out = (float*)d_out;

    cudaFuncSetAttribute(bn_conv_f16p,
                         cudaFuncAttributeMaxDynamicSharedMemorySize, SMEM_BYTES);
    bn_conv_f16p<<<GRID, 256, SMEM_BYTES>>>(x, gamma, beta, rmean, rvar, W, out);
}